// round 16
// baseline (speedup 1.0000x reference)
#include <cuda_runtime.h>
#include <cuda_fp16.h>
#include <cstdint>

// ============================================================================
// UnifiedRadialMLP via mma.sync m16n8k16 f16/f32-acc — base sm_100 PTX.
//
// R15 = R14 (N-split warp pairs) with two fixes:
//  1. LN statistics are PAIR-WIDE: each warp's quad-reduced partial S/Q for
//     its N-half goes through a small SMEM buffer (red) and both halves are
//     summed after the barrier that already orders the epilogue. (R14 used
//     half-channel stats -> rel_err 0.53.)
//  2. Weight XOR swizzle corrected: xsw(g) = ((g&1)<<2)|(g>>1) puts the
//     phase-varying g bit on u4-bit2, giving 8 distinct mod-8 uint4 columns
//     per LDS.128 phase (R14's ^g left 2-way conflicts).
// Structure: warp pair shares 32 rows; warp u computes N-half. B traffic/row
// is 4x lower than R13. h crosses the pair via SMEM (R8-proven layout).
// SMEM 107.8KB/CTA -> 2 CTAs/SM. 4 __syncthreads per tile.
// ============================================================================

namespace {

constexpr int D_IN  = 64;
constexpr int H     = 128;
constexpr int D_OUT = 64;
constexpr int NT    = 256;                 // 8 warps = 4 pairs
constexpr int TM    = 128;                 // 4 pairs x 32 rows
constexpr int SLICES  = 36;
constexpr int NBLOCKS = 8 * SLICES;        // 288 = 2 CTAs/SM x 144 SMs
constexpr float LN_EPS = 1e-5f;

// Weight rows unpadded (XOR swizzle). h rows: stride 72 words (==8 mod 32).
constexpr int W1W = 32;    // W1 row: 64 halves = 32 words
constexpr int WW  = 64;    // W2/W3 row: 128 halves = 64 words
constexpr int HWS = 72;

// SMEM layout (word offsets): 107,776 B total
constexpr int F_W1 = 0;                    // fp16 [128][32w]
constexpr int F_W2 = F_W1 + H * W1W;       // fp16 [128][64w]
constexpr int F_W3 = F_W2 + H * WW;        // fp16 [64][64w]
constexpr int F_H  = F_W3 + D_OUT * WW;    // fp16 [128][72w]
constexpr int F_B1 = F_H + TM * HWS;
constexpr int F_G1 = F_B1 + H, F_BE1 = F_G1 + H;
constexpr int F_B2 = F_BE1 + H, F_G2 = F_B2 + H, F_BE2 = F_G2 + H;
constexpr int F_B3 = F_BE2 + H;
constexpr int F_RED = F_B3 + D_OUT;        // float[128][4]: (S,Q) x 2 halves
constexpr int SMEM_WORDS = F_RED + TM * 4;
constexpr int SMEM_BYTES = SMEM_WORDS * 4;

// Paired-step half permutation within a 32-k super-block (R12-proven):
// half index = 32sb + 8t' + 4sp + 2fw + hp.
__device__ __forceinline__ int perm32h(int k) {
    return ((k >> 5) << 5) | (((k & 7) >> 1) << 3) | (((k >> 4) & 1) << 2)
         | (((k >> 3) & 1) << 1) | (k & 1);
}
// Phase-correct XOR swizzle: bit0 of g -> u4 bit2.
__device__ __forceinline__ int xsw(int g) { return ((g & 1) << 2) | (g >> 1); }
__device__ __forceinline__ int sw_half(int row, int k) {
    const int ph = perm32h(k);
    const int u4 = (ph >> 3) ^ xsw(row & 7);
    return (u4 << 3) | (ph & 7);
}

__device__ __forceinline__ void mma16(float d[4],
                                      uint32_t a0, uint32_t a1, uint32_t a2, uint32_t a3,
                                      uint32_t b0, uint32_t b1) {
    asm volatile(
        "mma.sync.aligned.m16n8k16.row.col.f32.f16.f16.f32 "
        "{%0,%1,%2,%3}, {%4,%5,%6,%7}, {%8,%9}, {%0,%1,%2,%3};"
        : "+f"(d[0]), "+f"(d[1]), "+f"(d[2]), "+f"(d[3])
        : "r"(a0), "r"(a1), "r"(a2), "r"(a3), "r"(b0), "r"(b1));
}
__device__ __forceinline__ float silu_f(float v) {
    const float hv = 0.5f * v;
    float th;
    asm("tanh.approx.f32 %0, %1;" : "=f"(th) : "f"(hv));
    return fmaf(hv, th, hv);
}
__device__ __forceinline__ uint32_t pack2(float lo, float hi) {
    const __half2 h = __floats2half2_rn(lo, hi);
    return *(const uint32_t*)&h;
}

// Phase A (pre-barrier): +bias, quad-reduced PARTIAL stats -> red[row][u].
__device__ __forceinline__ void epi_stats(float acc[8][2][4],
                                          float* __restrict__ smf,
                                          int offB, int ub, int m0,
                                          int g, int t, int c0) {
    float S[4] = {0, 0, 0, 0}, Q[4] = {0, 0, 0, 0};
    #pragma unroll
    for (int j = 0; j < 8; j++) {
        const float2 bb = *(const float2*)(smf + offB + ub + 8 * j + c0);
        #pragma unroll
        for (int r = 0; r < 4; r++) {
            float& u = acc[j][r >> 1][(r & 1) * 2];
            float& w = acc[j][r >> 1][(r & 1) * 2 + 1];
            u += bb.x; w += bb.y;
            S[r] += u + w;
            Q[r] += u * u + w * w;
        }
    }
    #pragma unroll
    for (int m = 1; m <= 2; m <<= 1)
        #pragma unroll
        for (int r = 0; r < 4; r++) {
            S[r] += __shfl_xor_sync(~0u, S[r], m);
            Q[r] += __shfl_xor_sync(~0u, Q[r], m);
        }
    if (t == 0) {
        const int u = ub >> 6;
        #pragma unroll
        for (int r = 0; r < 4; r++)
            *(float2*)(smf + F_RED + (m0 + g + 8 * r) * 4 + 2 * u) =
                make_float2(S[r], Q[r]);
    }
}

// Phase B (post-barrier): combine halves, LN+SiLU, pack fp16 -> SMEM h.
__device__ __forceinline__ void epi_finish(float acc[8][2][4],
                                           uint32_t* __restrict__ sm,
                                           const float* __restrict__ smf,
                                           int offG, int offBE,
                                           int ub, int m0, int g, int c0) {
    __half2* hp2 = (__half2*)sm;
    float mu[4], rs[4];
    #pragma unroll
    for (int r = 0; r < 4; r++) {
        const float2 p0 = *(const float2*)(smf + F_RED + (m0 + g + 8 * r) * 4);
        const float2 p1 = *(const float2*)(smf + F_RED + (m0 + g + 8 * r) * 4 + 2);
        const float S = p0.x + p1.x, Q = p0.y + p1.y;
        mu[r] = S * (1.f / H);
        rs[r] = rsqrtf(fmaf(-mu[r], mu[r], Q * (1.f / H)) + LN_EPS);
    }
    #pragma unroll
    for (int j = 0; j < 8; j++) {
        const float2 gg = *(const float2*)(smf + offG  + ub + 8 * j + c0);
        const float2 be = *(const float2*)(smf + offBE + ub + 8 * j + c0);
        const int jg = (ub >> 3) + j;
        const int wj = 8 * (jg >> 1) + c0 + (jg & 1);
        #pragma unroll
        for (int r = 0; r < 4; r++) {
            const float u = acc[j][r >> 1][(r & 1) * 2];
            const float w = acc[j][r >> 1][(r & 1) * 2 + 1];
            hp2[F_H + (m0 + g + 8 * r) * HWS + wj] = __floats2half2_rn(
                silu_f(fmaf((u - mu[r]) * rs[r], gg.x, be.x)),
                silu_f(fmaf((w - mu[r]) * rs[r], gg.y, be.y)));
        }
    }
}

__global__ void __launch_bounds__(NT, 2)
radial_mma(const float* __restrict__ x_g,
           const float* __restrict__ W1, const float* __restrict__ b1,
           const float* __restrict__ g1, const float* __restrict__ be1,
           const float* __restrict__ W2, const float* __restrict__ b2,
           const float* __restrict__ g2, const float* __restrict__ be2,
           const float* __restrict__ W3, const float* __restrict__ b3,
           float* __restrict__ out, int E, int ntiles) {
    extern __shared__ uint32_t sm[];
    float*  smf = (float*)sm;
    __half* w1h = (__half*)(sm + F_W1);
    __half* w2h = (__half*)(sm + F_W2);
    __half* w3h = (__half*)(sm + F_W3);

    const int tid  = threadIdx.x;
    const int warp = tid >> 5, lane = tid & 31;
    const int g = lane >> 2, t = lane & 3;
    const int n = blockIdx.x & 7, slice = blockIdx.x >> 3;
    const int pair = warp >> 1, u = warp & 1;
    const int m0 = pair * 32;
    const int c0 = 2 * t;
    const int ub = u * 64;
    const int swg = xsw(g);

    // ---- One-time: stage weights (fp16, perm32 + xsw swizzle) + params ----
    for (int i = tid; i < H * D_IN; i += NT) {
        const int r = i >> 6, k = i & 63;
        w1h[r * (2 * W1W) + sw_half(r, k)] =
            __float2half_rn(W1[(size_t)(n * H + r) * D_IN + k]);
    }
    for (int i = tid; i < H * H; i += NT) {
        const int r = i >> 7, k = i & 127;
        w2h[r * (2 * WW) + sw_half(r, k)] =
            __float2half_rn(W2[(size_t)n * H * H + (size_t)r * H + k]);
    }
    for (int i = tid; i < D_OUT * H; i += NT) {
        const int r = i >> 7, k = i & 127;
        w3h[r * (2 * WW) + sw_half(r, k)] =
            __float2half_rn(W3[(size_t)n * D_OUT * H + (size_t)r * H + k]);
    }
    if (tid < H) {
        smf[F_B1 + tid]  = b1 [n * H + tid];
        smf[F_G1 + tid]  = g1 [n * H + tid];
        smf[F_BE1 + tid] = be1[n * H + tid];
        smf[F_B2 + tid]  = b2 [n * H + tid];
        smf[F_G2 + tid]  = g2 [n * H + tid];
        smf[F_BE2 + tid] = be2[n * H + tid];
    }
    if (tid < D_OUT) smf[F_B3 + tid] = b3[n * D_OUT + tid];
    __syncthreads();

    for (int tile = slice; tile < ntiles; tile += SLICES) {
        const int e0 = tile * TM;
        int  ge[4];  bool vr[4];
        #pragma unroll
        for (int r = 0; r < 4; r++) {
            ge[r] = e0 + m0 + g + 8 * r;
            vr[r] = ge[r] < E;
        }

        // ==== GEMM1: D1-half[32, 64] = x @ W1^T (rows ub+8j+g) ====
        float acc[8][2][4];
        #pragma unroll
        for (int j = 0; j < 8; j++)
            #pragma unroll
            for (int p = 0; p < 2; p++)
                acc[j][p][0] = acc[j][p][1] = acc[j][p][2] = acc[j][p][3] = 0.f;

        #pragma unroll
        for (int sb = 0; sb < 2; sb++) {
            uint32_t Ax[4][4];
            #pragma unroll
            for (int r = 0; r < 4; r++) {
                if (vr[r]) {
                    const float* xr = x_g + (size_t)ge[r] * D_IN + 32 * sb;
                    const float2 e_a = *(const float2*)(xr + c0);
                    const float2 e_b = *(const float2*)(xr + c0 + 8);
                    const float2 o_a = *(const float2*)(xr + 16 + c0);
                    const float2 o_b = *(const float2*)(xr + 16 + c0 + 8);
                    Ax[r][0] = pack2(e_a.x, e_a.y);
                    Ax[r][1] = pack2(e_b.x, e_b.y);
                    Ax[r][2] = pack2(o_a.x, o_a.y);
                    Ax[r][3] = pack2(o_b.x, o_b.y);
                } else {
                    Ax[r][0] = Ax[r][1] = Ax[r][2] = Ax[r][3] = 0u;
                }
            }
            const int bu = ((4 * sb + t) ^ swg) << 2;
            #pragma unroll
            for (int j = 0; j < 8; j++) {
                const uint4 B = *(const uint4*)(sm + F_W1 + (ub + 8 * j + g) * W1W + bu);
                mma16(acc[j][0], Ax[0][0], Ax[1][0], Ax[0][1], Ax[1][1], B.x, B.y);
                mma16(acc[j][1], Ax[2][0], Ax[3][0], Ax[2][1], Ax[3][1], B.x, B.y);
                mma16(acc[j][0], Ax[0][2], Ax[1][2], Ax[0][3], Ax[1][3], B.z, B.w);
                mme_dummy:;
                mma16(acc[j][1], Ax[2][2], Ax[3][2], Ax[2][3], Ax[3][3], B.z, B.w);
            }
        }

        // epi1 phase A: partial stats -> red (red is safe: previous readers
        // finished before the previous tile's last barrier).
        epi_stats(acc, smf, F_B1, ub, m0, g, t, c0);
        __syncthreads();   // red visible; partner's prev GEMM3 h-reads done
        epi_finish(acc, sm, smf, F_G1, F_BE1, ub, m0, g, c0);
        __syncthreads();   // h complete (both halves)

        // ==== GEMM2: D2-half[32, 64] = h @ W2^T (full K=128) ====
        #pragma unroll
        for (int j = 0; j < 8; j++)
            #pragma unroll
            for (int p = 0; p < 2; p++)
                acc[j][p][0] = acc[j][p][1] = acc[j][p][2] = acc[j][p][3] = 0.f;
        #pragma unroll
        for (int sb = 0; sb < 4; sb++) {
            uint2 He[4], Ho[4];
            #pragma unroll
            for (int r = 0; r < 4; r++) {
                const int hb = F_H + (m0 + g + 8 * r) * HWS + 16 * sb;
                He[r] = *(const uint2*)(sm + hb + c0);
                Ho[r] = *(const uint2*)(sm + hb + 8 + c0);
            }
            const int bu = ((4 * sb + t) ^ swg) << 2;
            #pragma unroll
            for (int j = 0; j < 8; j++) {
                const uint4 B = *(const uint4*)(sm + F_W2 + (ub + 8 * j + g) * WW + bu);
                mma16(acc[j][0], He[0].x, He[1].x, He[0].y, He[1].y, B.x, B.y);
                mma16(acc[j][1], He[2].x, He[3].x, He[2].y, He[3].y, B.x, B.y);
                mma16(acc[j][0], Ho[0].x, Ho[1].x, Ho[0].y, Ho[1].y, B.z, B.w);
                mma16(acc[j][1], Ho[2].x, Ho[3].x, Ho[2].y, Ho[3].y, B.z, B.w);
            }
        }

        // epi2 phase A (red safe: epi1 red-reads finished before syncB < GEMM2)
        epi_stats(acc, smf, F_B2, ub, m0, g, t, c0);
        __syncthreads();   // red visible; all GEMM2 h-reads done
        epi_finish(acc, sm, smf, F_G2, F_BE2, ub, m0, g, c0);
        __syncthreads();   // h complete for GEMM3

        // ==== GEMM3: D3-half[32, 32] = h @ W3^T (rows u*32+8j+g) ====
        float a3[4][2][4];
        #pragma unroll
        for (int j = 0; j < 4; j++)
            #pragma unroll
            for (int p = 0; p < 2; p++)
                a3[j][p][0] = a3[j][p][1] = a3[j][p][2] = a3[j][p][3] = 0.f;
        #pragma unroll
        for (int sb = 0; sb < 4; sb++) {
            uint2 He[4], Ho[4];
            #pragma unroll
            for (int r = 0; r < 4; r++) {
                const int hb = F_H + (m0 + g + 8 * r) * HWS + 16 * sb;
                He[r] = *(const uint2*)(sm + hb + c0);
                Ho[r] = *(const uint2*)(sm + hb + 8 + c0);
            }
            const int bu = ((4 * sb + t) ^ swg) << 2;
            #pragma unroll
            for (int j = 0; j < 4; j++) {
                const uint4 B = *(const uint4*)(sm + F_W3 + (u * 32 + 8 * j + g) * WW + bu);
                mma16(a3[j][0], He[0].x, He[1].x, He[0].y, He[1].y, B.x, B.y);
                mma16(a3[j][1], He[2].x, He[3].x, He[2].y, He[3].y, B.x, B.y);
                mma16(a3[j][0], Ho[0].x, Ho[1].x, Ho[0].y, Ho[1].y, B.z, B.w);
                mma16(a3[j][1], Ho[2].x, Ho[3].x, Ho[2].y, Ho[3].y, B.z, B.w);
            }
        }

        // ==== Epilogue 3: +b3, STG.64 (own 32-col half of each row) ====
        #pragma unroll
        for (int j = 0; j < 4; j++) {
            const int cg = u * 32 + 8 * j + c0;
            const float2 bb = *(const float2*)(smf + F_B3 + cg);
            #pragma unroll
            for (int r = 0; r < 4; r++) {
                if (vr[r]) {
                    float* o = out + ((size_t)n * (size_t)E + (size_t)ge[r]) * D_OUT;
                    *(float2*)(o + cg) = make_float2(
                        a3[j][r >> 1][(r & 1) * 2]     + bb.x,
                        a3[j][r >> 1][(r & 1) * 2 + 1] + bb.y);
                }
            }
        }
    }
}

} // namespace

extern "C" void kernel_launch(void* const* d_in, const int* in_sizes, int n_in,
                              void* d_out, int out_size) {
    const float* x   = (const float*)d_in[0];
    const float* W1  = (const float*)d_in[1];
    const float* b1  = (const float*)d_in[2];
    const float* g1  = (const float*)d_in[3];
    const float* be1 = (const float*)d_in[4];
    const float* W2  = (const float*)d_in[5];
    const float* b2  = (const float*)d_in[6];
    const float* g2  = (const float*)d_in[7];
    const float* be2 = (const float*)d_in[8];
    const float* W3  = (const float*)d_in[9];
    const float* b3  = (const float*)d_in[10];
    float* out = (float*)d_out;

    const int E = in_sizes[0] / D_IN;
    const int ntiles = (E + TM - 1) / TM;

    cudaFuncSetAttribute(radial_mma,
                         cudaFuncAttributeMaxDynamicSharedMemorySize, SMEM_BYTES);

    radial_mma<<<NBLOCKS, NT, SMEM_BYTES>>>(
        x, W1, b1, g1, be1, W2, b2, g2, be2, W3, b3, out, E, ntiles);
}

// round 17
// speedup vs baseline: 1.0201x; 1.0201x over previous
#include <cuda_runtime.h>
#include <cuda_fp16.h>
#include <cstdint>

// ============================================================================
// UnifiedRadialMLP via mma.sync m16n8k16 f16/f32-acc — base sm_100 PTX.
//
// R16 = R15 (N-split warp pairs, pair-wide LN stats, fixed weight swizzle)
// with the two regression fixes:
//  1. h stride 72 -> 68 words: bank = (4g+2t)%32, distinct for all 32 lanes.
//     (72 gave (8g+2t): g and g+4 collided -> every h load 2-way conflicted.)
//  2. In-loop __syncthreads -> bar.sync (pair+1), 64: pair-scoped hardware
//     barriers. h/red rows are pair-disjoint, weights read-only, so pairs
//     drift independently (restores R5-style overlap lost in R15).
// ============================================================================

namespace {

constexpr int D_IN  = 64;
constexpr int H     = 128;
constexpr int D_OUT = 64;
constexpr int NT    = 256;                 // 8 warps = 4 pairs
constexpr int TM    = 128;                 // 4 pairs x 32 rows
constexpr int SLICES  = 36;
constexpr int NBLOCKS = 8 * SLICES;        // 288 = 2 CTAs/SM x 144 SMs
constexpr float LN_EPS = 1e-5f;

// Weight rows unpadded (XOR swizzle). h rows: stride 68 words (==4 mod 32:
// uint2 banks 4g+2t all distinct).
constexpr int W1W = 32;    // W1 row: 64 halves = 32 words
constexpr int WW  = 64;    // W2/W3 row: 128 halves = 64 words
constexpr int HWS = 68;

// SMEM layout (word offsets)
constexpr int F_W1 = 0;                    // fp16 [128][32w]
constexpr int F_W2 = F_W1 + H * W1W;       // fp16 [128][64w]
constexpr int F_W3 = F_W2 + H * WW;        // fp16 [64][64w]
constexpr int F_H  = F_W3 + D_OUT * WW;    // fp16 [128][68w]
constexpr int F_B1 = F_H + TM * HWS;
constexpr int F_G1 = F_B1 + H, F_BE1 = F_G1 + H;
constexpr int F_B2 = F_BE1 + H, F_G2 = F_B2 + H, F_BE2 = F_G2 + H;
constexpr int F_B3 = F_BE2 + H;
constexpr int F_RED = F_B3 + D_OUT;        // float[128][4]: (S,Q) x 2 halves
constexpr int SMEM_WORDS = F_RED + TM * 4;
constexpr int SMEM_BYTES = SMEM_WORDS * 4; // 105,728 B -> 2 CTAs/SM fits

// Paired-step half permutation within a 32-k super-block (R12-proven):
// half index = 32sb + 8t' + 4sp + 2fw + hp.
__device__ __forceinline__ int perm32h(int k) {
    return ((k >> 5) << 5) | (((k & 7) >> 1) << 3) | (((k >> 4) & 1) << 2)
         | (((k >> 3) & 1) << 1) | (k & 1);
}
// Phase-correct XOR swizzle: bit0 of g -> u4 bit2.
__device__ __forceinline__ int xsw(int g) { return ((g & 1) << 2) | (g >> 1); }
__device__ __forceinline__ int sw_half(int row, int k) {
    const int ph = perm32h(k);
    const int u4 = (ph >> 3) ^ xsw(row & 7);
    return (u4 << 3) | (ph & 7);
}

// Pair-scoped named barrier: both warps of the pair (64 threads), ids 1..4.
#define BAR_PAIR(pid) \
    asm volatile("bar.sync %0, 64;" :: "r"((pid) + 1) : "memory")

__device__ __forceinline__ void mma16(float d[4],
                                      uint32_t a0, uint32_t a1, uint32_t a2, uint32_t a3,
                                      uint32_t b0, uint32_t b1) {
    asm volatile(
        "mma.sync.aligned.m16n8k16.row.col.f32.f16.f16.f32 "
        "{%0,%1,%2,%3}, {%4,%5,%6,%7}, {%8,%9}, {%0,%1,%2,%3};"
        : "+f"(d[0]), "+f"(d[1]), "+f"(d[2]), "+f"(d[3])
        : "r"(a0), "r"(a1), "r"(a2), "r"(a3), "r"(b0), "r"(b1));
}
__device__ __forceinline__ float silu_f(float v) {
    const float hv = 0.5f * v;
    float th;
    asm("tanh.approx.f32 %0, %1;" : "=f"(th) : "f"(hv));
    return fmaf(hv, th, hv);
}
__device__ __forceinline__ uint32_t pack2(float lo, float hi) {
    const __half2 h = __floats2half2_rn(lo, hi);
    return *(const uint32_t*)&h;
}

// Phase A (pre-barrier): +bias, quad-reduced PARTIAL stats -> red[row][u].
__device__ __forceinline__ void epi_stats(float acc[8][2][4],
                                          float* __restrict__ smf,
                                          int offB, int ub, int m0,
                                          int g, int t, int c0) {
    float S[4] = {0, 0, 0, 0}, Q[4] = {0, 0, 0, 0};
    #pragma unroll
    for (int j = 0; j < 8; j++) {
        const float2 bb = *(const float2*)(smf + offB + ub + 8 * j + c0);
        #pragma unroll
        for (int r = 0; r < 4; r++) {
            float& u = acc[j][r >> 1][(r & 1) * 2];
            float& w = acc[j][r >> 1][(r & 1) * 2 + 1];
            u += bb.x; w += bb.y;
            S[r] += u + w;
            Q[r] += u * u + w * w;
        }
    }
    #pragma unroll
    for (int m = 1; m <= 2; m <<= 1)
        #pragma unroll
        for (int r = 0; r < 4; r++) {
            S[r] += __shfl_xor_sync(~0u, S[r], m);
            Q[r] += __shfl_xor_sync(~0u, Q[r], m);
        }
    if (t == 0) {
        const int u = ub >> 6;
        #pragma unroll
        for (int r = 0; r < 4; r++)
            *(float2*)(smf + F_RED + (m0 + g + 8 * r) * 4 + 2 * u) =
                make_float2(S[r], Q[r]);
    }
}

// Phase B (post-barrier): combine halves, LN+SiLU, pack fp16 -> SMEM h.
__device__ __forceinline__ void epi_finish(float acc[8][2][4],
                                           uint32_t* __restrict__ sm,
                                           const float* __restrict__ smf,
                                           int offG, int offBE,
                                           int ub, int m0, int g, int c0) {
    __half2* hp2 = (__half2*)sm;
    float mu[4], rs[4];
    #pragma unroll
    for (int r = 0; r < 4; r++) {
        const float2 p0 = *(const float2*)(smf + F_RED + (m0 + g + 8 * r) * 4);
        const float2 p1 = *(const float2*)(smf + F_RED + (m0 + g + 8 * r) * 4 + 2);
        const float S = p0.x + p1.x, Q = p0.y + p1.y;
        mu[r] = S * (1.f / H);
        rs[r] = rsqrtf(fmaf(-mu[r], mu[r], Q * (1.f / H)) + LN_EPS);
    }
    #pragma unroll
    for (int j = 0; j < 8; j++) {
        const float2 gg = *(const float2*)(smf + offG  + ub + 8 * j + c0);
        const float2 be = *(const float2*)(smf + offBE + ub + 8 * j + c0);
        const int jg = (ub >> 3) + j;
        const int wj = 8 * (jg >> 1) + c0 + (jg & 1);
        #pragma unroll
        for (int r = 0; r < 4; r++) {
            const float u = acc[j][r >> 1][(r & 1) * 2];
            const float w = acc[j][r >> 1][(r & 1) * 2 + 1];
            hp2[F_H + (m0 + g + 8 * r) * HWS + wj] = __floats2half2_rn(
                silu_f(fmaf((u - mu[r]) * rs[r], gg.x, be.x)),
                silu_f(fmaf((w - mu[r]) * rs[r], gg.y, be.y)));
        }
    }
}

__global__ void __launch_bounds__(NT, 2)
radial_mma(const float* __restrict__ x_g,
           const float* __restrict__ W1, const float* __restrict__ b1,
           const float* __restrict__ g1, const float* __restrict__ be1,
           const float* __restrict__ W2, const float* __restrict__ b2,
           const float* __restrict__ g2, const float* __restrict__ be2,
           const float* __restrict__ W3, const float* __restrict__ b3,
           float* __restrict__ out, int E, int ntiles) {
    extern __shared__ uint32_t sm[];
    float*  smf = (float*)sm;
    __half* w1h = (__half*)(sm + F_W1);
    __half* w2h = (__half*)(sm + F_W2);
    __half* w3h = (__half*)(sm + F_W3);

    const int tid  = threadIdx.x;
    const int warp = tid >> 5, lane = tid & 31;
    const int g = lane >> 2, t = lane & 3;
    const int n = blockIdx.x & 7, slice = blockIdx.x >> 3;
    const int pair = warp >> 1, u = warp & 1;
    const int m0 = pair * 32;
    const int c0 = 2 * t;
    const int ub = u * 64;
    const int swg = xsw(g);

    // ---- One-time: stage weights (fp16, perm32 + xsw swizzle) + params ----
    for (int i = tid; i < H * D_IN; i += NT) {
        const int r = i >> 6, k = i & 63;
        w1h[r * (2 * W1W) + sw_half(r, k)] =
            __float2half_rn(W1[(size_t)(n * H + r) * D_IN + k]);
    }
    for (int i = tid; i < H * H; i += NT) {
        const int r = i >> 7, k = i & 127;
        w2h[r * (2 * WW) + sw_half(r, k)] =
            __float2half_rn(W2[(size_t)n * H * H + (size_t)r * H + k]);
    }
    for (int i = tid; i < D_OUT * H; i += NT) {
        const int r = i >> 7, k = i & 127;
        w3h[r * (2 * WW) + sw_half(r, k)] =
            __float2half_rn(W3[(size_t)n * D_OUT * H + (size_t)r * H + k]);
    }
    if (tid < H) {
        smf[F_B1 + tid]  = b1 [n * H + tid];
        smf[F_G1 + tid]  = g1 [n * H + tid];
        smf[F_BE1 + tid] = be1[n * H + tid];
        smf[F_B2 + tid]  = b2 [n * H + tid];
        smf[F_G2 + tid]  = g2 [n * H + tid];
        smf[F_BE2 + tid] = be2[n * H + tid];
    }
    if (tid < D_OUT) smf[F_B3 + tid] = b3[n * D_OUT + tid];
    __syncthreads();   // weights/params visible to all warps (one-time)

    for (int tile = slice; tile < ntiles; tile += SLICES) {
        const int e0 = tile * TM;
        int  ge[4];  bool vr[4];
        #pragma unroll
        for (int r = 0; r < 4; r++) {
            ge[r] = e0 + m0 + g + 8 * r;
            vr[r] = ge[r] < E;
        }

        // ==== GEMM1: D1-half[32, 64] = x @ W1^T (rows ub+8j+g) ====
        float acc[8][2][4];
        #pragma unroll
        for (int j = 0; j < 8; j++)
            #pragma unroll
            for (int p = 0; p < 2; p++)
                acc[j][p][0] = acc[j][p][1] = acc[j][p][2] = acc[j][p][3] = 0.f;

        #pragma unroll
        for (int sb = 0; sb < 2; sb++) {
            uint32_t Ax[4][4];
            #pragma unroll
            for (int r = 0; r < 4; r++) {
                if (vr[r]) {
                    const float* xr = x_g + (size_t)ge[r] * D_IN + 32 * sb;
                    const float2 e_a = *(const float2*)(xr + c0);
                    const float2 e_b = *(const float2*)(xr + c0 + 8);
                    const float2 o_a = *(const float2*)(xr + 16 + c0);
                    const float2 o_b = *(const float2*)(xr + 16 + c0 + 8);
                    Ax[r][0] = pack2(e_a.x, e_a.y);
                    Ax[r][1] = pack2(e_b.x, e_b.y);
                    Ax[r][2] = pack2(o_a.x, o_a.y);
                    Ax[r][3] = pack2(o_b.x, o_b.y);
                } else {
                    Ax[r][0] = Ax[r][1] = Ax[r][2] = Ax[r][3] = 0u;
                }
            }
            const int bu = ((4 * sb + t) ^ swg) << 2;
            #pragma unroll
            for (int j = 0; j < 8; j++) {
                const uint4 B = *(const uint4*)(sm + F_W1 + (ub + 8 * j + g) * W1W + bu);
                mma16(acc[j][0], Ax[0][0], Ax[1][0], Ax[0][1], Ax[1][1], B.x, B.y);
                mma16(acc[j][1], Ax[2][0], Ax[3][0], Ax[2][1], Ax[3][1], B.x, B.y);
                mma16(acc[j][0], Ax[0][2], Ax[1][2], Ax[0][3], Ax[1][3], B.z, B.w);
                mma16(acc[j][1], Ax[2][2], Ax[3][2], Ax[2][3], Ax[3][3], B.z, B.w);
            }
        }

        // epi1 phase A: partial stats -> red (safe: pair's previous readers
        // finished before the previous tile's last pair barrier).
        epi_stats(acc, smf, F_B1, ub, m0, g, t, c0);
        BAR_PAIR(pair);    // red visible; partner's prev GEMM3 h-reads done
        epi_finish(acc, sm, smf, F_G1, F_BE1, ub, m0, g, c0);
        BAR_PAIR(pair);    // h complete (both halves)

        // ==== GEMM2: D2-half[32, 64] = h @ W2^T (full K=128) ====
        #pragma unroll
        for (int j = 0; j < 8; j++)
            #pragma unroll
            for (int p = 0; p < 2; p++)
                acc[j][p][0] = acc[j][p][1] = acc[j][p][2] = acc[j][p][3] = 0.f;
        #pragma unroll
        for (int sb = 0; sb < 4; sb++) {
            uint2 He[4], Ho[4];
            #pragma unroll
            for (int r = 0; r < 4; r++) {
                const int hb = F_H + (m0 + g + 8 * r) * HWS + 16 * sb;
                He[r] = *(const uint2*)(sm + hb + c0);
                Ho[r] = *(const uint2*)(sm + hb + 8 + c0);
            }
            const int bu = ((4 * sb + t) ^ swg) << 2;
            #pragma unroll
            for (int j = 0; j < 8; j++) {
                const uint4 B = *(const uint4*)(sm + F_W2 + (ub + 8 * j + g) * WW + bu);
                mma16(acc[j][0], He[0].x, He[1].x, He[0].y, He[1].y, B.x, B.y);
                mma16(acc[j][1], He[2].x, He[3].x, He[2].y, He[3].y, B.x, B.y);
                mma16(acc[j][0], Ho[0].x, Ho[1].x, Ho[0].y, Ho[1].y, B.z, B.w);
                mma16(acc[j][1], Ho[2].x, Ho[3].x, Ho[2].y, Ho[3].y, B.z, B.w);
            }
        }

        // epi2 phase A (red safe: epi1 red-reads done before the barrier
        // preceding GEMM2).
        epi_stats(acc, smf, F_B2, ub, m0, g, t, c0);
        BAR_PAIR(pair);    // red visible; pair's GEMM2 h-reads done
        epi_finish(acc, sm, smf, F_G2, F_BE2, ub, m0, g, c0);
        BAR_PAIR(pair);    // h complete for GEMM3

        // ==== GEMM3: D3-half[32, 32] = h @ W3^T (rows u*32+8j+g) ====
        float a3[4][2][4];
        #pragma unroll
        for (int j = 0; j < 4; j++)
            #pragma unroll
            for (int p = 0; p < 2; p++)
                a3[j][p][0] = a3[j][p][1] = a3[j][p][2] = a3[j][p][3] = 0.f;
        #pragma unroll
        for (int sb = 0; sb < 4; sb++) {
            uint2 He[4], Ho[4];
            #pragma unroll
            for (int r = 0; r < 4; r++) {
                const int hb = F_H + (m0 + g + 8 * r) * HWS + 16 * sb;
                He[r] = *(const uint2*)(sm + hb + c0);
                Ho[r] = *(const uint2*)(sm + hb + 8 + c0);
            }
            const int bu = ((4 * sb + t) ^ swg) << 2;
            #pragma unroll
            for (int j = 0; j < 4; j++) {
                const uint4 B = *(const uint4*)(sm + F_W3 + (u * 32 + 8 * j + g) * WW + bu);
                mma16(a3[j][0], He[0].x, He[1].x, He[0].y, He[1].y, B.x, B.y);
                mma16(a3[j][1], He[2].x, He[3].x, He[2].y, He[3].y, B.x, B.y);
                mma16(a3[j][0], Ho[0].x, Ho[1].x, Ho[0].y, Ho[1].y, B.z, B.w);
                mma16(a3[j][1], Ho[2].x, Ho[3].x, Ho[2].y, Ho[3].y, B.z, B.w);
            }
        }

        // ==== Epilogue 3: +b3, STG.64 (own 32-col half of each row) ====
        #pragma unroll
        for (int j = 0; j < 4; j++) {
            const int cg = u * 32 + 8 * j + c0;
            const float2 bb = *(const float2*)(smf + F_B3 + cg);
            #pragma unroll
            for (int r = 0; r < 4; r++) {
                if (vr[r]) {
                    float* o = out + ((size_t)n * (size_t)E + (size_t)ge[r]) * D_OUT;
                    *(float2*)(o + cg) = make_float2(
                        a3[j][r >> 1][(r & 1) * 2]     + bb.x,
                        a3[j][r >> 1][(r & 1) * 2 + 1] + bb.y);
                }
            }
        }
        // next tile: GEMM1 touches no h; the pair barrier before epi_finish
        // orders this tile's GEMM3 h-reads against next tile's h-writes.
    }
}

} // namespace

extern "C" void kernel_launch(void* const* d_in, const int* in_sizes, int n_in,
                              void* d_out, int out_size) {
    const float* x   = (const float*)d_in[0];
    const float* W1  = (const float*)d_in[1];
    const float* b1  = (const float*)d_in[2];
    const float* g1  = (const float*)d_in[3];
    const float* be1 = (const float*)d_in[4];
    const float* W2  = (const float*)d_in[5];
    const float* b2  = (const float*)d_in[6];
    const float* g2  = (const float*)d_in[7];
    const float* be2 = (const float*)d_in[8];
    const float* W3  = (const float*)d_in[9];
    const float* b3  = (const float*)d_in[10];
    float* out = (float*)d_out;

    const int E = in_sizes[0] / D_IN;
    const int ntiles = (E + TM - 1) / TM;

    cudaFuncSetAttribute(radial_mma,
                         cudaFuncAttributeMaxDynamicSharedMemorySize, SMEM_BYTES);

    radial_mma<<<NBLOCKS, NT, SMEM_BYTES>>>(
        x, W1, b1, g1, be1, W2, b2, g2, be2, W3, b3, out, E, ntiles);
}